// round 15
// baseline (speedup 1.0000x reference)
#include <cuda_runtime.h>
#include <cuda_bf16.h>
#include <float.h>
#include <math.h>

#define R_ROIS 1000
#define N_CLASS 81
#define N_FG 80
#define IMG_H 600.0f
#define IMG_W 800.0f
#define SCORE_THRESH 0.05f
#define NMS_THRESH 0.5f
#define CAP 1024      // per-class candidate capacity (pow2 for legacy bitonic)
#define FAST 128      // matrix-NMS fast-path capacity
#define CSTRIDE 32    // 128B padding between per-class counters

#define TAIL_VEC   ((R_ROIS - FAST) * 5 / 4)   // 1090 float4 per class (out tail)
#define LTAIL_VEC  ((R_ROIS - FAST) / 4)       // 218  float4 per class (label tail)

// Scratch (no cudaMalloc). g_cnt zero-initialized at module load and reset
// by kernel B each launch -> deterministic across graph replays.
__device__ int    g_cnt[N_FG * CSTRIDE];
__device__ float  g_cp[N_FG * CAP];
__device__ int    g_cr[N_FG * CAP];
__device__ float4 g_cbox[N_FG * CAP];   // decoded+clamped (y0,x0,y1,x1)

// ---------------------------------------------------------------------------
// Kernel A: softmax (one WARP per RoI) + candidate emission WITH box decode.
// (exact R9 body)
// ---------------------------------------------------------------------------
__global__ __launch_bounds__(256) void softmax_kernel(const float* __restrict__ roi_score,
                                                      const float* __restrict__ roi,
                                                      const float* __restrict__ roi_loc) {
    const int r = (blockIdx.x * blockDim.x + threadIdx.x) >> 5;   // RoI index
    const int lane = threadIdx.x & 31;
    if (r >= R_ROIS) return;

    const float* sc = roi_score + r * N_CLASS;
    int c0 = lane, c1 = lane + 32, c2 = lane + 64;
    float s0 = sc[c0];
    float s1 = (c1 < N_CLASS) ? sc[c1] : -FLT_MAX;
    float s2 = (c2 < N_CLASS) ? sc[c2] : -FLT_MAX;

    float m = fmaxf(s0, fmaxf(s1, s2));
#pragma unroll
    for (int o = 16; o > 0; o >>= 1) m = fmaxf(m, __shfl_xor_sync(0xffffffffu, m, o));

    float e0 = expf(s0 - m);
    float e1 = (c1 < N_CLASS) ? expf(s1 - m) : 0.0f;
    float e2 = (c2 < N_CLASS) ? expf(s2 - m) : 0.0f;
    float sum = e0 + e1 + e2;
#pragma unroll
    for (int o = 16; o > 0; o >>= 1) sum += __shfl_xor_sync(0xffffffffu, sum, o);
    float inv = 1.0f / sum;

    float p0 = e0 * inv, p1 = e1 * inv, p2 = e2 * inv;

    float ry0 = roi[r * 4 + 0], rx0 = roi[r * 4 + 1];
    float ry1 = roi[r * 4 + 2], rx1 = roi[r * 4 + 3];
    float h = ry1 - ry0, w = rx1 - rx0;
    float cy = ry0 + 0.5f * h, cx = rx0 + 0.5f * w;

#pragma unroll
    for (int slot = 0; slot < 3; slot++) {
        int c = (slot == 0) ? c0 : (slot == 1) ? c1 : c2;
        float p = (slot == 0) ? p0 : (slot == 1) ? p1 : p2;
        if (c >= 1 && c < N_CLASS && p > SCORE_THRESH) {
            int fg = c - 1;
            int pos = atomicAdd(&g_cnt[fg * CSTRIDE], 1);
            if (pos < CAP) {
                const float* lc = roi_loc + r * (N_CLASS * 4) + c * 4;
                float dy = lc[0] * 0.1f, dx = lc[1] * 0.1f;
                float dh = lc[2] * 0.2f, dw = lc[3] * 0.2f;
                float ny = dy * h + cy, nx = dx * w + cx;
                float nh = expf(dh) * h, nw = expf(dw) * w;
                float4 b;
                b.x = fminf(fmaxf(ny - 0.5f * nh, 0.0f), IMG_H);  // y0
                b.y = fminf(fmaxf(nx - 0.5f * nw, 0.0f), IMG_W);  // x0
                b.z = fminf(fmaxf(ny + 0.5f * nh, 0.0f), IMG_H);  // y1
                b.w = fminf(fmaxf(nx + 0.5f * nw, 0.0f), IMG_W);  // x1
                g_cp[fg * CAP + pos] = p;
                g_cr[fg * CAP + pos] = r;
                g_cbox[fg * CAP + pos] = b;
            }
        }
    }
}

// ---------------------------------------------------------------------------
// Kernel B: one CTA per foreground class. Front: spec loads issued first,
// then static tail stores fired into the load-latency shadow. Fast path
// (nv <= 128): 2-way rank sort -> 2-way suppression matrix -> scan ->
// head-only epilogue. (R9 body otherwise)
// ---------------------------------------------------------------------------
__global__ __launch_bounds__(256) void nms_kernel(const float* __restrict__ roi,
                                                  const float* __restrict__ roi_loc,
                                                  float* __restrict__ out,
                                                  float* __restrict__ labels) {
    const int fg = blockIdx.x;        // 0..79
    const int c = fg + 1;             // class 1..80
    const int tid = threadIdx.x;
    const int item = tid & (FAST - 1);
    const int half = tid >> 7;        // 0 or 1
    const int NT = 256;

    __shared__ float skey[CAP];
    __shared__ int   sidx[CAP];
    // fast path
    __shared__ float sy0[FAST], sx0[FAST], sy1[FAST], sx1[FAST], sar[FAST], ssk[FAST];
    __shared__ int   sprank[FAST];    // upper-half partial ranks
    __shared__ int   srk[FAST];       // final rank per item
    __shared__ unsigned long long smA0[FAST], smA1[FAST], smB0[FAST], smB1[FAST];
    __shared__ unsigned long long sd0, sd1;
    // legacy path
    __shared__ float sb[CAP * 4];
    __shared__ float sarea[CAP];
    __shared__ unsigned char skeep[CAP];

    float* oc = out + (size_t)fg * R_ROIS * 5;
    float* lb = labels ? labels + (size_t)fg * R_ROIS : nullptr;

    // 1) speculative candidate loads FIRST (start the DRAM latency clock);
    //    stale data beyond nv is never consumed -> deterministic
    float myk = 0.0f; int myr = 0; float4 mybox = make_float4(0.f, 0.f, 0.f, 0.f);
    if (tid < FAST) {
        myk = g_cp[fg * CAP + tid];
        myr = g_cr[fg * CAP + tid];
        mybox = g_cbox[fg * CAP + tid];
    }
    int nv = g_cnt[fg * CSTRIDE];

    // 2) static tail stores fired into the load shadow (fire-and-forget).
    //    If nv > FAST, the legacy path below overwrites all rows anyway.
    {
        const float4 z4 = make_float4(0.f, 0.f, 0.f, 0.f);
        float4* t4 = (float4*)(oc + FAST * 5);
#pragma unroll 1
        for (int i = tid; i < TAIL_VEC; i += NT) t4[i] = z4;
        if (lb) {
            const float4 n4 = make_float4(-1.f, -1.f, -1.f, -1.f);
            float4* l4 = (float4*)(lb + FAST);
#pragma unroll 1
            for (int i = tid; i < LTAIL_VEC; i += NT) l4[i] = n4;
        }
    }

    if (tid < FAST) { skey[tid] = myk; sidx[tid] = myr; }
    if (nv > CAP) nv = CAP;
    __syncthreads();
    if (tid == 0) g_cnt[fg * CSTRIDE] = 0;   // reset for next launch

    if (nv <= FAST) {
        // ---- 3) partial rank: half 0 covers m in [0,nv/2), half 1 the rest
        int pr = 0;
        if (item < nv) {
            float ik = skey[item];
            int   ii = sidx[item];
            int mlo = (half == 0) ? 0 : (nv >> 1);
            int mhi = (half == 0) ? (nv >> 1) : nv;
#pragma unroll 1
            for (int m = mlo; m < mhi; m++) {
                float km = skey[m];
                int   im = sidx[m];
                pr += ((km > ik) || (km == ik && im < ii)) ? 1 : 0;
            }
        }
        if (half == 1 && item < nv) sprank[item] = pr;
        __syncthreads();

        // ---- 4) combine + scatter full record to sorted position ---------
        int rank = 0;
        float bar = (mybox.z - mybox.x) * (mybox.w - mybox.y);
        if (half == 0 && tid < nv) {
            rank = pr + sprank[tid];
            sy0[rank] = mybox.x; sx0[rank] = mybox.y;
            sy1[rank] = mybox.z; sx1[rank] = mybox.w;
            sar[rank] = bar;     ssk[rank] = myk;
            srk[tid]  = rank;
        }
        __syncthreads();

        // ---- 5) suppression matrix, 2 threads per row (interleaved j) ----
        if (item < nv) {
            int ri = (half == 0) ? rank : srk[item];
            float iy0 = sy0[ri], ix0 = sx0[ri];
            float iy1 = sy1[ri], ix1 = sx1[ri];
            float iar = sar[ri];
            unsigned long long m0 = 0ull, m1 = 0ull;
#pragma unroll 1
            for (int j = ri + 1 + half; j < nv; j += 2) {
                float ty = fmaxf(iy0, sy0[j]);
                float tx = fmaxf(ix0, sx0[j]);
                float by = fminf(iy1, sy1[j]);
                float bx = fminf(ix1, sx1[j]);
                float inter = fmaxf(by - ty, 0.0f) * fmaxf(bx - tx, 0.0f);
                float iou = inter / (iar + sar[j] - inter + 1e-9f);
                if (iou > NMS_THRESH) {
                    if (j < 64) m0 |= 1ull << j;
                    else        m1 |= 1ull << (j - 64);
                }
            }
            if (half == 0) { smA0[ri] = m0; smA1[ri] = m1; }
            else           { smB0[ri] = m0; smB1[ri] = m1; }
        }
        __syncthreads();

        // ---- 6) serial greedy scan (pure ALU chain; loads off-chain) -----
        if (tid == 0) {
            unsigned long long d0 = 0ull, d1 = 0ull;
#pragma unroll 4
            for (int i = 0; i < nv; i++) {
                unsigned long long m0 = smA0[i] | smB0[i];   // addr dep on i only
                unsigned long long m1 = smA1[i] | smB1[i];
                unsigned long long bit = (i < 64) ? (d0 >> i) : (d1 >> (i - 64));
                if (!(bit & 1ull)) { d0 |= m0; d1 |= m1; }
            }
            sd0 = d0; sd1 = d1;
        }
        __syncthreads();

        // ---- 7) head-only epilogue: rows [0,FAST); tail already written --
        unsigned long long d0 = sd0, d1 = sd1;
        if (tid < FAST) {
            int r = tid;
            bool kp = false;
            if (r < nv) {
                unsigned long long bit = (r < 64) ? (d0 >> r) : (d1 >> (r - 64));
                kp = !(bit & 1ull);
            }
            oc[r * 5 + 0] = kp ? sy0[r] : 0.0f;
            oc[r * 5 + 1] = kp ? sx0[r] : 0.0f;
            oc[r * 5 + 2] = kp ? sy1[r] : 0.0f;
            oc[r * 5 + 3] = kp ? sx1[r] : 0.0f;
            oc[r * 5 + 4] = kp ? ssk[r] : 0.0f;
            if (lb) lb[r] = kp ? (float)fg : -1.0f;
        }
        return;
    }

    // ---------------- legacy path (nv > FAST; uniform branch) -------------
    // (writes ALL 1000 rows itself; overwrites the early tail stores)
#pragma unroll 1
    for (int t = tid; t < nv; t += NT) {
        skey[t] = g_cp[fg * CAP + t];
        sidx[t] = g_cr[fg * CAP + t];
    }
    __syncthreads();

    int P = 1;
    while (P < nv) P <<= 1;
    for (int i = nv + tid; i < P; i += NT) { skey[i] = -FLT_MAX; sidx[i] = 0x7fffffff; }
    __syncthreads();
    for (int k = 2; k <= P; k <<= 1) {
        for (int j = k >> 1; j > 0; j >>= 1) {
            for (int i = tid; i < P; i += NT) {
                int ixj = i ^ j;
                if (ixj > i) {
                    float a = skey[i],  b = skey[ixj];
                    int   ia = sidx[i], ib = sidx[ixj];
                    bool desc = ((i & k) == 0);
                    bool before_ba = (b > a) || (b == a && ib < ia);
                    bool before_ab = (a > b) || (a == b && ia < ib);
                    if (desc ? before_ba : before_ab) {
                        skey[i] = b;  skey[ixj] = a;
                        sidx[i] = ib; sidx[ixj] = ia;
                    }
                }
            }
            __syncthreads();
        }
    }

#pragma unroll 1
    for (int kk = tid; kk < nv; kk += NT) {
        int r = sidx[kk];
        float y0 = roi[r * 4 + 0], x0 = roi[r * 4 + 1];
        float y1 = roi[r * 4 + 2], x1 = roi[r * 4 + 3];
        float h = y1 - y0, w = x1 - x0;
        float cy = y0 + 0.5f * h, cx = x0 + 0.5f * w;
        const float* lc = roi_loc + r * (N_CLASS * 4) + c * 4;
        float dy = lc[0] * 0.1f, dx = lc[1] * 0.1f;
        float dh = lc[2] * 0.2f, dw = lc[3] * 0.2f;
        float ny = dy * h + cy, nx = dx * w + cx;
        float nh = expf(dh) * h, nw = expf(dw) * w;
        float by0 = fminf(fmaxf(ny - 0.5f * nh, 0.0f), IMG_H);
        float bx0 = fminf(fmaxf(nx - 0.5f * nw, 0.0f), IMG_W);
        float by1 = fminf(fmaxf(ny + 0.5f * nh, 0.0f), IMG_H);
        float bx1 = fminf(fmaxf(nx + 0.5f * nw, 0.0f), IMG_W);
        sb[kk * 4 + 0] = by0; sb[kk * 4 + 1] = bx0;
        sb[kk * 4 + 2] = by1; sb[kk * 4 + 3] = bx1;
        sarea[kk] = (by1 - by0) * (bx1 - bx0);
        skeep[kk] = 1;
    }
    __syncthreads();

    if (tid < 32) {
#pragma unroll 1
        for (int i = 0; i < nv; i++) {
            if (skeep[i]) {
                float iy0 = sb[i * 4 + 0], ix0 = sb[i * 4 + 1];
                float iy1 = sb[i * 4 + 2], ix1 = sb[i * 4 + 3];
                float iar = sarea[i];
#pragma unroll 1
                for (int jj = i + 1 + tid; jj < nv; jj += 32) {
                    if (skeep[jj]) {
                        float ty = fmaxf(iy0, sb[jj * 4 + 0]);
                        float tx = fmaxf(ix0, sb[jj * 4 + 1]);
                        float by = fminf(iy1, sb[jj * 4 + 2]);
                        float bx = fminf(ix1, sb[jj * 4 + 3]);
                        float inter = fmaxf(by - ty, 0.0f) * fmaxf(bx - tx, 0.0f);
                        float iou = inter / (iar + sarea[jj] - inter + 1e-9f);
                        if (iou > NMS_THRESH) skeep[jj] = 0;
                    }
                }
            }
            __syncwarp();
        }
    }
    __syncthreads();

#pragma unroll 1
    for (int r = tid; r < R_ROIS; r += NT) {
        bool kp = (r < nv) && skeep[r];
        oc[r * 5 + 0] = kp ? sb[r * 4 + 0] : 0.0f;
        oc[r * 5 + 1] = kp ? sb[r * 4 + 1] : 0.0f;
        oc[r * 5 + 2] = kp ? sb[r * 4 + 2] : 0.0f;
        oc[r * 5 + 3] = kp ? sb[r * 4 + 3] : 0.0f;
        oc[r * 5 + 4] = kp ? skey[r]       : 0.0f;
        if (lb) lb[r] = kp ? (float)fg : -1.0f;
    }
}

extern "C" void kernel_launch(void* const* d_in, const int* in_sizes, int n_in,
                              void* d_out, int out_size) {
    const float* roi       = (const float*)d_in[0];  // [1000,4]
    const float* roi_loc   = (const float*)d_in[1];  // [1000,324]
    const float* roi_score = (const float*)d_in[2];  // [1000,81]

    float* out = (float*)d_out;
    const int out_elems   = N_FG * R_ROIS * 5;  // 400000
    const int label_elems = N_FG * R_ROIS;      // 80000
    float* labels = (out_size >= out_elems + label_elems) ? (out + out_elems)
                                                          : nullptr;

    softmax_kernel<<<(R_ROIS * 32 + 255) / 256, 256>>>(roi_score, roi, roi_loc);
    nms_kernel<<<N_FG, 256>>>(roi, roi_loc, out, labels);
}

// round 16
// speedup vs baseline: 1.1191x; 1.1191x over previous
#include <cuda_runtime.h>
#include <cuda_bf16.h>
#include <float.h>
#include <math.h>

#define R_ROIS 1000
#define N_CLASS 81
#define N_FG 80
#define IMG_H 600.0f
#define IMG_W 800.0f
#define SCORE_THRESH 0.05f
#define NMS_THRESH 0.5f
#define CAP 1024      // per-class candidate capacity (pow2 for legacy bitonic)
#define FAST 128      // matrix-NMS fast-path capacity
#define CSTRIDE 32    // 128B padding between per-class counters

#define TAIL_VEC   ((R_ROIS - FAST) * 5 / 4)   // 1090 float4 per class (out tail)
#define LTAIL_VEC  ((R_ROIS - FAST) / 4)       // 218  float4 per class (label tail)

// Scratch (no cudaMalloc). g_cnt zero-initialized at module load and reset
// by kernel B each launch -> deterministic across graph replays.
__device__ int    g_cnt[N_FG * CSTRIDE];
__device__ float  g_cp[N_FG * CAP];
__device__ int    g_cr[N_FG * CAP];
__device__ float4 g_cbox[N_FG * CAP];   // decoded+clamped (y0,x0,y1,x1)

// ---------------------------------------------------------------------------
// Kernel A: static output tail (rows [FAST,1000) of every class) + softmax
// (one WARP per RoI) + candidate emission WITH box decode. Tail stores are
// issued first: fire-and-forget, overlapping the softmax load latency.
// ---------------------------------------------------------------------------
__global__ __launch_bounds__(256) void softmax_kernel(const float* __restrict__ roi_score,
                                                      const float* __restrict__ roi,
                                                      const float* __restrict__ roi_loc,
                                                      float* __restrict__ out,
                                                      float* __restrict__ labels) {
    const int gtid = blockIdx.x * blockDim.x + threadIdx.x;   // 0..31999
    const int NTOT = ((R_ROIS * 32 + 255) / 256) * 256;       // 32000

    // ---- static tail: out rows [FAST,1000) = 0, labels = -1 --------------
    {
        const float4 z4 = make_float4(0.f, 0.f, 0.f, 0.f);
#pragma unroll 1
        for (int i = gtid; i < N_FG * TAIL_VEC; i += NTOT) {
            int fg = i / TAIL_VEC;
            int off = i - fg * TAIL_VEC;
            float4* p = (float4*)(out + (size_t)fg * R_ROIS * 5 + FAST * 5);
            p[off] = z4;
        }
        if (labels) {
            const float4 n4 = make_float4(-1.f, -1.f, -1.f, -1.f);
#pragma unroll 1
            for (int i = gtid; i < N_FG * LTAIL_VEC; i += NTOT) {
                int fg = i / LTAIL_VEC;
                int off = i - fg * LTAIL_VEC;
                float4* p = (float4*)(labels + (size_t)fg * R_ROIS + FAST);
                p[off] = n4;
            }
        }
    }

    const int r = gtid >> 5;          // RoI index
    const int lane = threadIdx.x & 31;
    if (r >= R_ROIS) return;

    const float* sc = roi_score + r * N_CLASS;
    int c0 = lane, c1 = lane + 32, c2 = lane + 64;
    float s0 = sc[c0];
    float s1 = (c1 < N_CLASS) ? sc[c1] : -FLT_MAX;
    float s2 = (c2 < N_CLASS) ? sc[c2] : -FLT_MAX;

    float m = fmaxf(s0, fmaxf(s1, s2));
#pragma unroll
    for (int o = 16; o > 0; o >>= 1) m = fmaxf(m, __shfl_xor_sync(0xffffffffu, m, o));

    float e0 = expf(s0 - m);
    float e1 = (c1 < N_CLASS) ? expf(s1 - m) : 0.0f;
    float e2 = (c2 < N_CLASS) ? expf(s2 - m) : 0.0f;
    float sum = e0 + e1 + e2;
#pragma unroll
    for (int o = 16; o > 0; o >>= 1) sum += __shfl_xor_sync(0xffffffffu, sum, o);
    float inv = 1.0f / sum;

    float p0 = e0 * inv, p1 = e1 * inv, p2 = e2 * inv;

    float ry0 = roi[r * 4 + 0], rx0 = roi[r * 4 + 1];
    float ry1 = roi[r * 4 + 2], rx1 = roi[r * 4 + 3];
    float h = ry1 - ry0, w = rx1 - rx0;
    float cy = ry0 + 0.5f * h, cx = rx0 + 0.5f * w;

#pragma unroll
    for (int slot = 0; slot < 3; slot++) {
        int c = (slot == 0) ? c0 : (slot == 1) ? c1 : c2;
        float p = (slot == 0) ? p0 : (slot == 1) ? p1 : p2;
        if (c >= 1 && c < N_CLASS && p > SCORE_THRESH) {
            int fg = c - 1;
            int pos = atomicAdd(&g_cnt[fg * CSTRIDE], 1);
            if (pos < CAP) {
                const float* lc = roi_loc + r * (N_CLASS * 4) + c * 4;
                float dy = lc[0] * 0.1f, dx = lc[1] * 0.1f;
                float dh = lc[2] * 0.2f, dw = lc[3] * 0.2f;
                float ny = dy * h + cy, nx = dx * w + cx;
                float nh = expf(dh) * h, nw = expf(dw) * w;
                float4 b;
                b.x = fminf(fmaxf(ny - 0.5f * nh, 0.0f), IMG_H);  // y0
                b.y = fminf(fmaxf(nx - 0.5f * nw, 0.0f), IMG_W);  // x0
                b.z = fminf(fmaxf(ny + 0.5f * nh, 0.0f), IMG_H);  // y1
                b.w = fminf(fmaxf(nx + 0.5f * nw, 0.0f), IMG_W);  // x1
                g_cp[fg * CAP + pos] = p;
                g_cr[fg * CAP + pos] = r;
                g_cbox[fg * CAP + pos] = b;
            }
        }
    }
}

// ---------------------------------------------------------------------------
// Kernel B: one CTA per foreground class. Fast path (nv <= 128): speculative
// load -> 2-way split rank sort -> 2-way split suppression matrix -> scan ->
// head-only epilogue (tail already written by kernel A).  (R9 body)
// ---------------------------------------------------------------------------
__global__ __launch_bounds__(256) void nms_kernel(const float* __restrict__ roi,
                                                  const float* __restrict__ roi_loc,
                                                  float* __restrict__ out,
                                                  float* __restrict__ labels) {
    const int fg = blockIdx.x;        // 0..79
    const int c = fg + 1;             // class 1..80
    const int tid = threadIdx.x;
    const int item = tid & (FAST - 1);
    const int half = tid >> 7;        // 0 or 1
    const int NT = 256;

    __shared__ float skey[CAP];
    __shared__ int   sidx[CAP];
    // fast path
    __shared__ float sy0[FAST], sx0[FAST], sy1[FAST], sx1[FAST], sar[FAST], ssk[FAST];
    __shared__ int   sprank[FAST];    // upper-half partial ranks
    __shared__ int   srk[FAST];       // final rank per item
    __shared__ unsigned long long smA0[FAST], smA1[FAST], smB0[FAST], smB1[FAST];
    __shared__ unsigned long long sd0, sd1;
    // legacy path
    __shared__ float sb[CAP * 4];
    __shared__ float sarea[CAP];
    __shared__ unsigned char skeep[CAP];

    // speculative candidate load: independent of the g_cnt load (stale data
    // beyond nv is never consumed -> deterministic)
    float myk = 0.0f; int myr = 0; float4 mybox = make_float4(0.f, 0.f, 0.f, 0.f);
    if (tid < FAST) {
        myk = g_cp[fg * CAP + tid];
        myr = g_cr[fg * CAP + tid];
        mybox = g_cbox[fg * CAP + tid];
        skey[tid] = myk;
        sidx[tid] = myr;
    }
    int nv = g_cnt[fg * CSTRIDE];
    if (nv > CAP) nv = CAP;
    __syncthreads();
    if (tid == 0) g_cnt[fg * CSTRIDE] = 0;   // reset for next launch

    if (nv <= FAST) {
        // ---- 1) partial rank: half 0 covers m in [0,nv/2), half 1 the rest
        int pr = 0;
        if (item < nv) {
            float ik = skey[item];
            int   ii = sidx[item];
            int mlo = (half == 0) ? 0 : (nv >> 1);
            int mhi = (half == 0) ? (nv >> 1) : nv;
#pragma unroll 1
            for (int m = mlo; m < mhi; m++) {
                float km = skey[m];
                int   im = sidx[m];
                pr += ((km > ik) || (km == ik && im < ii)) ? 1 : 0;
            }
        }
        if (half == 1 && item < nv) sprank[item] = pr;
        __syncthreads();

        // ---- 2) combine + scatter full record to sorted position ---------
        int rank = 0;
        float bar = (mybox.z - mybox.x) * (mybox.w - mybox.y);
        if (half == 0 && tid < nv) {
            rank = pr + sprank[tid];
            sy0[rank] = mybox.x; sx0[rank] = mybox.y;
            sy1[rank] = mybox.z; sx1[rank] = mybox.w;
            sar[rank] = bar;     ssk[rank] = myk;
            srk[tid]  = rank;
        }
        __syncthreads();

        // ---- 3) suppression matrix, 2 threads per row (interleaved j) ----
        if (item < nv) {
            int ri = (half == 0) ? rank : srk[item];
            float iy0 = sy0[ri], ix0 = sx0[ri];
            float iy1 = sy1[ri], ix1 = sx1[ri];
            float iar = sar[ri];
            unsigned long long m0 = 0ull, m1 = 0ull;
#pragma unroll 1
            for (int j = ri + 1 + half; j < nv; j += 2) {
                float ty = fmaxf(iy0, sy0[j]);
                float tx = fmaxf(ix0, sx0[j]);
                float by = fminf(iy1, sy1[j]);
                float bx = fminf(ix1, sx1[j]);
                float inter = fmaxf(by - ty, 0.0f) * fmaxf(bx - tx, 0.0f);
                float iou = inter / (iar + sar[j] - inter + 1e-9f);
                if (iou > NMS_THRESH) {
                    if (j < 64) m0 |= 1ull << j;
                    else        m1 |= 1ull << (j - 64);
                }
            }
            if (half == 0) { smA0[ri] = m0; smA1[ri] = m1; }
            else           { smB0[ri] = m0; smB1[ri] = m1; }
        }
        __syncthreads();

        // ---- 4) serial greedy scan (pure ALU chain; loads off-chain) -----
        if (tid == 0) {
            unsigned long long d0 = 0ull, d1 = 0ull;
#pragma unroll 4
            for (int i = 0; i < nv; i++) {
                unsigned long long m0 = smA0[i] | smB0[i];   // addr dep on i only
                unsigned long long m1 = smA1[i] | smB1[i];
                unsigned long long bit = (i < 64) ? (d0 >> i) : (d1 >> (i - 64));
                if (!(bit & 1ull)) { d0 |= m0; d1 |= m1; }
            }
            sd0 = d0; sd1 = d1;
        }
        __syncthreads();

        // ---- 5) head-only epilogue: rows [0,FAST); tail written by A -----
        unsigned long long d0 = sd0, d1 = sd1;
        float* oc = out + (size_t)fg * R_ROIS * 5;
        if (tid < FAST) {
            int r = tid;
            bool kp = false;
            if (r < nv) {
                unsigned long long bit = (r < 64) ? (d0 >> r) : (d1 >> (r - 64));
                kp = !(bit & 1ull);
            }
            oc[r * 5 + 0] = kp ? sy0[r] : 0.0f;
            oc[r * 5 + 1] = kp ? sx0[r] : 0.0f;
            oc[r * 5 + 2] = kp ? sy1[r] : 0.0f;
            oc[r * 5 + 3] = kp ? sx1[r] : 0.0f;
            oc[r * 5 + 4] = kp ? ssk[r] : 0.0f;
            if (labels)
                labels[(size_t)fg * R_ROIS + r] = kp ? (float)fg : -1.0f;
        }
        return;
    }

    // ---------------- legacy path (nv > FAST; uniform branch) -------------
    // (writes ALL 1000 rows itself; overwrites A's tail with correct values)
#pragma unroll 1
    for (int t = tid; t < nv; t += NT) {
        skey[t] = g_cp[fg * CAP + t];
        sidx[t] = g_cr[fg * CAP + t];
    }
    __syncthreads();

    int P = 1;
    while (P < nv) P <<= 1;
    for (int i = nv + tid; i < P; i += NT) { skey[i] = -FLT_MAX; sidx[i] = 0x7fffffff; }
    __syncthreads();
    for (int k = 2; k <= P; k <<= 1) {
        for (int j = k >> 1; j > 0; j >>= 1) {
            for (int i = tid; i < P; i += NT) {
                int ixj = i ^ j;
                if (ixj > i) {
                    float a = skey[i],  b = skey[ixj];
                    int   ia = sidx[i], ib = sidx[ixj];
                    bool desc = ((i & k) == 0);
                    bool before_ba = (b > a) || (b == a && ib < ia);
                    bool before_ab = (a > b) || (a == b && ia < ib);
                    if (desc ? before_ba : before_ab) {
                        skey[i] = b;  skey[ixj] = a;
                        sidx[i] = ib; sidx[ixj] = ia;
                    }
                }
            }
            __syncthreads();
        }
    }

#pragma unroll 1
    for (int kk = tid; kk < nv; kk += NT) {
        int r = sidx[kk];
        float y0 = roi[r * 4 + 0], x0 = roi[r * 4 + 1];
        float y1 = roi[r * 4 + 2], x1 = roi[r * 4 + 3];
        float h = y1 - y0, w = x1 - x0;
        float cy = y0 + 0.5f * h, cx = x0 + 0.5f * w;
        const float* lc = roi_loc + r * (N_CLASS * 4) + c * 4;
        float dy = lc[0] * 0.1f, dx = lc[1] * 0.1f;
        float dh = lc[2] * 0.2f, dw = lc[3] * 0.2f;
        float ny = dy * h + cy, nx = dx * w + cx;
        float nh = expf(dh) * h, nw = expf(dw) * w;
        float by0 = fminf(fmaxf(ny - 0.5f * nh, 0.0f), IMG_H);
        float bx0 = fminf(fmaxf(nx - 0.5f * nw, 0.0f), IMG_W);
        float by1 = fminf(fmaxf(ny + 0.5f * nh, 0.0f), IMG_H);
        float bx1 = fminf(fmaxf(nx + 0.5f * nw, 0.0f), IMG_W);
        sb[kk * 4 + 0] = by0; sb[kk * 4 + 1] = bx0;
        sb[kk * 4 + 2] = by1; sb[kk * 4 + 3] = bx1;
        sarea[kk] = (by1 - by0) * (bx1 - bx0);
        skeep[kk] = 1;
    }
    __syncthreads();

    if (tid < 32) {
#pragma unroll 1
        for (int i = 0; i < nv; i++) {
            if (skeep[i]) {
                float iy0 = sb[i * 4 + 0], ix0 = sb[i * 4 + 1];
                float iy1 = sb[i * 4 + 2], ix1 = sb[i * 4 + 3];
                float iar = sarea[i];
#pragma unroll 1
                for (int jj = i + 1 + tid; jj < nv; jj += 32) {
                    if (skeep[jj]) {
                        float ty = fmaxf(iy0, sb[jj * 4 + 0]);
                        float tx = fmaxf(ix0, sb[jj * 4 + 1]);
                        float by = fminf(iy1, sb[jj * 4 + 2]);
                        float bx = fminf(ix1, sb[jj * 4 + 3]);
                        float inter = fmaxf(by - ty, 0.0f) * fmaxf(bx - tx, 0.0f);
                        float iou = inter / (iar + sarea[jj] - inter + 1e-9f);
                        if (iou > NMS_THRESH) skeep[jj] = 0;
                    }
                }
            }
            __syncwarp();
        }
    }
    __syncthreads();

    float* oc = out + (size_t)fg * R_ROIS * 5;
#pragma unroll 1
    for (int r = tid; r < R_ROIS; r += NT) {
        bool kp = (r < nv) && skeep[r];
        oc[r * 5 + 0] = kp ? sb[r * 4 + 0] : 0.0f;
        oc[r * 5 + 1] = kp ? sb[r * 4 + 1] : 0.0f;
        oc[r * 5 + 2] = kp ? sb[r * 4 + 2] : 0.0f;
        oc[r * 5 + 3] = kp ? sb[r * 4 + 3] : 0.0f;
        oc[r * 5 + 4] = kp ? skey[r]       : 0.0f;
        if (labels)
            labels[(size_t)fg * R_ROIS + r] = kp ? (float)fg : -1.0f;
    }
}

extern "C" void kernel_launch(void* const* d_in, const int* in_sizes, int n_in,
                              void* d_out, int out_size) {
    const float* roi       = (const float*)d_in[0];  // [1000,4]
    const float* roi_loc   = (const float*)d_in[1];  // [1000,324]
    const float* roi_score = (const float*)d_in[2];  // [1000,81]

    float* out = (float*)d_out;
    const int out_elems   = N_FG * R_ROIS * 5;  // 400000
    const int label_elems = N_FG * R_ROIS;      // 80000
    float* labels = (out_size >= out_elems + label_elems) ? (out + out_elems)
                                                          : nullptr;

    softmax_kernel<<<(R_ROIS * 32 + 255) / 256, 256>>>(roi_score, roi, roi_loc, out, labels);
    nms_kernel<<<N_FG, 256>>>(roi, roi_loc, out, labels);
}